// round 17
// baseline (speedup 1.0000x reference)
#include <cuda_runtime.h>
#include <cuda_fp16.h>
#include <cstdint>

// Problem constants: N=512, A=1024, B=64, C=16
#define NN   512
#define AA   1024
#define BB   64
#define CC   16
#define OUTW (AA + BB)   // 1088

#define NGRP   16            // row groups of 32
#define GSZ    32
#define NTILES (NGRP * (NGRP + 1) / 2)   // 136

#define LOG2E 1.44269504088896340736f

// ---------------- device scratch ----------------
// M (pre-scaled by log2e) fp16, b-paired layout:
// g_Mp[row*512 + q*16 + c] = half2( M[row][2q][c], M[row][2q+1][c] ), q 0..31, c 0..15
__device__ uint32_t g_Mp[NN * 512];
__device__ __half g_xh[NN * AA];     // x in fp16
__device__ __half g_Wh[AA * AA];     // W * log2e in fp16, native [k][n]

// ---------------- helpers ----------------
__device__ __forceinline__ uint32_t smem_u32(const void* p) {
    uint32_t a;
    asm("{ .reg .u64 t; cvta.to.shared.u64 t, %1; cvt.u32.u64 %0, t; }" : "=r"(a) : "l"(p));
    return a;
}
#define LDMATRIX_X4(r0, r1, r2, r3, addr) \
    asm volatile("ldmatrix.sync.aligned.m8n8.x4.shared.b16 {%0,%1,%2,%3}, [%4];" \
        : "=r"(r0), "=r"(r1), "=r"(r2), "=r"(r3) : "r"(addr))
#define LDMATRIX_X4_T(r0, r1, r2, r3, addr) \
    asm volatile("ldmatrix.sync.aligned.m8n8.x4.trans.shared.b16 {%0,%1,%2,%3}, [%4];" \
        : "=r"(r0), "=r"(r1), "=r"(r2), "=r"(r3) : "r"(addr))

__device__ __forceinline__ void mma_f16(float d[4], const uint32_t a[4], const uint32_t b[2]) {
    asm volatile(
        "mma.sync.aligned.m16n8k16.row.col.f32.f16.f16.f32 "
        "{%0,%1,%2,%3}, {%4,%5,%6,%7}, {%8,%9}, {%0,%1,%2,%3};"
        : "+f"(d[0]), "+f"(d[1]), "+f"(d[2]), "+f"(d[3])
        : "r"(a[0]), "r"(a[1]), "r"(a[2]), "r"(a[3]), "r"(b[0]), "r"(b[1]));
}

__device__ __forceinline__ __half2 u2h(uint32_t u) {
    return *reinterpret_cast<__half2*>(&u);
}
__device__ __forceinline__ uint32_t h2u(__half2 v) {
    return *reinterpret_cast<uint32_t*>(&v);
}
// two fp16 exp2s in one MUFU op
__device__ __forceinline__ __half2 ex2_h2(__half2 v) {
    uint32_t r, in = h2u(v);
    asm("ex2.approx.f16x2 %0, %1;" : "=r"(r) : "r"(in));
    return u2h(r);
}

// half2 (l1(b_even), l1(b_odd)) over 16 comps held in 16 half2 regs
__device__ __forceinline__ __half2 l1_h2(const uint32_t* mj, const uint32_t* mi) {
    __half2 d[16];
#pragma unroll
    for (int c = 0; c < 16; c++)
        d[c] = __habs2(__hsub2(u2h(mj[c]), u2h(mi[c])));
#pragma unroll
    for (int st = 8; st >= 1; st >>= 1)
#pragma unroll
        for (int c = 0; c < st; c++)
            d[c] = __hadd2(d[c], d[c + st]);
    return d[0];
}

// ---------------------------------------------------------------------------
// Fused prep (pure streaming, no smem):
//   blocks [0,256):   copy x -> out, convert x -> g_xh; first 128 also
//                     init out[:,1024:] = -1.
//   blocks [256,768): elementwise W * log2e -> g_Wh (fp16, [k][n]).
// ---------------------------------------------------------------------------
__global__ __launch_bounds__(256)
void prep_kernel(const float* __restrict__ x, const float* __restrict__ W,
                 float* __restrict__ out) {
    if (blockIdx.x < 256) {
        int t = blockIdx.x * 256 + threadIdx.x;     // handles 8 floats
        int row  = t >> 7;
        int col8 = (t & 127) * 8;
        const float4* src = reinterpret_cast<const float4*>(x + (size_t)row * AA + col8);
        float4 a = src[0], b = src[1];
        float4* dst = reinterpret_cast<float4*>(out + (size_t)row * OUTW + col8);
        dst[0] = a; dst[1] = b;
        __half2 p0 = __float22half2_rn(make_float2(a.x, a.y));
        __half2 p1 = __float22half2_rn(make_float2(a.z, a.w));
        __half2 p2 = __float22half2_rn(make_float2(b.x, b.y));
        __half2 p3 = __float22half2_rn(make_float2(b.z, b.w));
        uint4 o; o.x = h2u(p0); o.y = h2u(p1); o.z = h2u(p2); o.w = h2u(p3);
        reinterpret_cast<uint4*>(g_xh)[t] = o;
        if (blockIdx.x < 128) {
            int idx = blockIdx.x * 256 + threadIdx.x;   // 0..32767
            int i = idx >> 6;
            int b2 = idx & 63;
            out[(size_t)i * OUTW + AA + b2] = -1.0f;
        }
    } else {
        int t = (blockIdx.x - 256) * 256 + threadIdx.x; // handles 8 floats
        const float4* src = reinterpret_cast<const float4*>(W) + 2 * (size_t)t;
        float4 a = src[0], b = src[1];
        __half2 p0 = __float22half2_rn(make_float2(a.x * LOG2E, a.y * LOG2E));
        __half2 p1 = __float22half2_rn(make_float2(a.z * LOG2E, a.w * LOG2E));
        __half2 p2 = __float22half2_rn(make_float2(b.x * LOG2E, b.y * LOG2E));
        __half2 p3 = __float22half2_rn(make_float2(b.z * LOG2E, b.w * LOG2E));
        uint4 o; o.x = h2u(p0); o.y = h2u(p1); o.z = h2u(p2); o.w = h2u(p3);
        reinterpret_cast<uint4*>(g_Wh)[t] = o;
    }
}

// ---------------------------------------------------------------------------
// GEMM via mma.sync fp16 m16n8k16. Block 64x64, 128 threads (4 warps 2x2),
// K chunked by 64, swizzled smem, register prefetch.
// A: row-major [m][k]; B: native [k][n], fragments via ldmatrix.x4.trans.
// Epilogue -> b-paired fp16 g_Mp (nt and nt+2 fragments pair b with b+1).
// ---------------------------------------------------------------------------
#define BK 64
#define NCH (AA / BK)   // 16

__global__ __launch_bounds__(128)
void gemm_mma_kernel() {
    __shared__ __align__(1024) __half sA[64 * BK];   // 8 KB  [m-row][k]
    __shared__ __align__(1024) __half sB[64 * BK];   // 8 KB  [k-row][n]

    const int tid = threadIdx.x;
    const int wid = tid >> 5;
    const int l   = tid & 31;
    const int mw  = wid & 1;
    const int nw  = wid >> 1;
    const int row0 = blockIdx.y * 64;
    const int col0 = blockIdx.x * 64;

    const uint32_t sA_addr = smem_u32(sA);
    const uint32_t sB_addr = smem_u32(sB);

    float acc[2][4][4];
#pragma unroll
    for (int mt = 0; mt < 2; mt++)
#pragma unroll
        for (int nt = 0; nt < 4; nt++)
#pragma unroll
            for (int e = 0; e < 4; e++) acc[mt][nt][e] = 0.0f;

    uint4 pa[4], pb[4];
#pragma unroll
    for (int s = 0; s < 4; s++) {
        int ch = tid + s * 128;
        int r = ch >> 3, u = ch & 7;
        pa[s] = *reinterpret_cast<const uint4*>(g_xh + (size_t)(row0 + r) * AA + u * 8);
        pb[s] = *reinterpret_cast<const uint4*>(g_Wh + (size_t)r * AA + col0 + u * 8);
    }

    const int aRow0 = ((l >> 3) & 1) * 8 + (l & 7) + mw * 32;
    const int aKsel = (l >> 4);
    const int bRowL = ((l >> 3) & 1) * 8 + (l & 7);   // k-row within 16-step
    const int bUsel = (l >> 4);                        // n 16B-unit selector
    const int swz   = (l & 7);

    for (int c = 0; c < NCH; c++) {
#pragma unroll
        for (int s = 0; s < 4; s++) {
            int ch = tid + s * 128;
            int r = ch >> 3, u = ch & 7;
            uint32_t off = (uint32_t)(r * 128 + ((u ^ (r & 7)) << 4));
            *reinterpret_cast<uint4*>(reinterpret_cast<char*>(sA) + off) = pa[s];
            *reinterpret_cast<uint4*>(reinterpret_cast<char*>(sB) + off) = pb[s];
        }
        __syncthreads();

        if (c + 1 < NCH) {
            int k0 = (c + 1) * BK;
#pragma unroll
            for (int s = 0; s < 4; s++) {
                int ch = tid + s * 128;
                int r = ch >> 3, u = ch & 7;
                pa[s] = *reinterpret_cast<const uint4*>(g_xh + (size_t)(row0 + r) * AA + k0 + u * 8);
                pb[s] = *reinterpret_cast<const uint4*>(g_Wh + (size_t)(k0 + r) * AA + col0 + u * 8);
            }
        }

#pragma unroll
        for (int ks = 0; ks < 4; ks++) {
            uint32_t af[2][4], bf[4][2];
#pragma unroll
            for (int mt = 0; mt < 2; mt++) {
                int row = aRow0 + mt * 16;
                uint32_t u = (uint32_t)(ks * 2 + aKsel);
                uint32_t addr = sA_addr + (uint32_t)(row * 128) + (((u ^ swz)) << 4);
                LDMATRIX_X4(af[mt][0], af[mt][1], af[mt][2], af[mt][3], addr);
            }
#pragma unroll
            for (int h = 0; h < 2; h++) {
                int row = ks * 16 + bRowL;
                uint32_t u = (uint32_t)(nw * 4 + h * 2 + bUsel);
                uint32_t addr = sB_addr + (uint32_t)(row * 128) + (((u ^ (row & 7))) << 4);
                uint32_t r0, r1, r2, r3;
                LDMATRIX_X4_T(r0, r1, r2, r3, addr);
                bf[h * 2 + 0][0] = r0; bf[h * 2 + 0][1] = r1;
                bf[h * 2 + 1][0] = r2; bf[h * 2 + 1][1] = r3;
            }
#pragma unroll
            for (int mt = 0; mt < 2; mt++)
#pragma unroll
                for (int nt = 0; nt < 4; nt++)
                    mma_f16(acc[mt][nt], af[mt], bf[nt]);
        }
        __syncthreads();
    }

    // Epilogue: b-paired half2 layout. nt and nt+2 are 16 columns apart ->
    // same c, adjacent b (even/odd) within this warp's 32-col span.
    const int g = l >> 2;
    const int cc2 = (l & 3) * 2;
    const int qw = (col0 + nw * 32) >> 5;   // b-pair index (0..31), same for the warp
#pragma unroll
    for (int mt = 0; mt < 2; mt++) {
        int rowA = row0 + mw * 32 + mt * 16 + g;
#pragma unroll
        for (int ntp = 0; ntp < 2; ntp++) {
            int c = ntp * 8 + cc2;
            uint32_t w00 = h2u(__floats2half2_rn(acc[mt][ntp][0], acc[mt][ntp + 2][0]));
            uint32_t w01 = h2u(__floats2half2_rn(acc[mt][ntp][1], acc[mt][ntp + 2][1]));
            uint32_t w10 = h2u(__floats2half2_rn(acc[mt][ntp][2], acc[mt][ntp + 2][2]));
            uint32_t w11 = h2u(__floats2half2_rn(acc[mt][ntp][3], acc[mt][ntp + 2][3]));
            *reinterpret_cast<uint2*>(&g_Mp[(size_t)rowA * 512 + qw * 16 + c]) =
                make_uint2(w00, w01);
            *reinterpret_cast<uint2*>(&g_Mp[(size_t)(rowA + 8) * 512 + qw * 16 + c]) =
                make_uint2(w10, w11);
        }
    }
}

// ---------------------------------------------------------------------------
// Pairwise, b-paired fp16x2 math. Triangular tiles over 16 groups of 32 rows,
// 136 blocks x 512 threads (single wave). Thread (q = t&31 b-pair, isp = t>>5
// in 0..15): owns 2 i-rows, loops 32 j-rows (prefetch depth 2).
// Per (i,j): one 16-reg HSUB2/HABS2/HADD2 tree -> half2(l1_even, l1_odd),
// one ex2.approx.f16x2, one HADD2 accumulate (fp16 sums are exact 0/1 ints).
// ---------------------------------------------------------------------------
__global__ __launch_bounds__(512)
void pairwise_kernel(float* __restrict__ out) {
    const int t   = threadIdx.x;
    const int q   = t & 31;        // b-pair index
    const int isp = t >> 5;        // 0..15

    // decode triangular tile: offset(g) = g*(33-g)/2 for NGRP=16
    int tt = blockIdx.x;
    int gi = 0;
#pragma unroll
    for (int g = 1; g < NGRP; g++)
        if ((g * (2 * NGRP + 1 - g)) / 2 <= tt) gi = g;
    int gj = gi + (tt - (gi * (2 * NGRP + 1 - gi)) / 2);

    const int i0 = gi * GSZ + isp * 2;
    const int j0 = gj * GSZ;

    __shared__ uint32_t red[16][16][32];   // 32 KB: [jj][isp][q] half2 sums

    const uint4* Mp4 = reinterpret_cast<const uint4*>(g_Mp);  // row stride 128

    // load 2 i-rows (16 u32 = 4 uint4 each)
    uint32_t mi[2][16];
#pragma unroll
    for (int k = 0; k < 2; k++) {
#pragma unroll
        for (int v = 0; v < 4; v++) {
            uint4 w = Mp4[(size_t)(i0 + k) * 128 + q * 4 + v];
            mi[k][4 * v + 0] = w.x; mi[k][4 * v + 1] = w.y;
            mi[k][4 * v + 2] = w.z; mi[k][4 * v + 3] = w.w;
        }
    }

    __half2 acc_i[2];
    acc_i[0] = u2h(0u); acc_i[1] = u2h(0u);

    // prefetch depth 2 on j-rows
    uint32_t jb[2][16];
#pragma unroll
    for (int p = 0; p < 2; p++) {
#pragma unroll
        for (int v = 0; v < 4; v++) {
            uint4 w = Mp4[(size_t)(j0 + p) * 128 + q * 4 + v];
            jb[p][4 * v + 0] = w.x; jb[p][4 * v + 1] = w.y;
            jb[p][4 * v + 2] = w.z; jb[p][4 * v + 3] = w.w;
        }
    }

    for (int half = 0; half < 2; half++) {
#pragma unroll
        for (int jj = 0; jj < 16; jj++) {
            const int jg = half * 16 + jj;
            uint32_t mj[16];
#pragma unroll
            for (int c = 0; c < 16; c++) mj[c] = jb[jg & 1][c];
            if (jg + 2 < GSZ) {
#pragma unroll
                for (int v = 0; v < 4; v++) {
                    uint4 w = Mp4[(size_t)(j0 + jg + 2) * 128 + q * 4 + v];
                    jb[jg & 1][4 * v + 0] = w.x; jb[jg & 1][4 * v + 1] = w.y;
                    jb[jg & 1][4 * v + 2] = w.z; jb[jg & 1][4 * v + 3] = w.w;
                }
            }

            __half2 e0 = ex2_h2(__hneg2(l1_h2(mj, mi[0])));
            __half2 e1 = ex2_h2(__hneg2(l1_h2(mj, mi[1])));
            acc_i[0] = __hadd2(acc_i[0], e0);
            acc_i[1] = __hadd2(acc_i[1], e1);
            red[jj][isp][q] = h2u(__hadd2(e0, e1));
        }
        __syncthreads();
        // j-side flush for this half (off-diagonal tiles only)
        if (gi != gj) {
            int jj = t >> 5;        // 0..15
            int qq = t & 31;
            __half2 s = u2h(0u);
#pragma unroll
            for (int k = 0; k < 16; k++)
                s = __hadd2(s, u2h(red[jj][k][qq]));
            float2 f = __half22float2(s);
            float* dst = out + (size_t)(j0 + half * 16 + jj) * OUTW + AA + 2 * qq;
            atomicAdd(dst, f.x);
            atomicAdd(dst + 1, f.y);
        }
        __syncthreads();
    }

    // i-side: atomic add per owned row (2 b-channels each)
#pragma unroll
    for (int k = 0; k < 2; k++) {
        float2 f = __half22float2(acc_i[k]);
        float* dst = out + (size_t)(i0 + k) * OUTW + AA + 2 * q;
        atomicAdd(dst, f.x);
        atomicAdd(dst + 1, f.y);
    }
}

// ---------------------------------------------------------------------------
extern "C" void kernel_launch(void* const* d_in, const int* in_sizes, int n_in,
                              void* d_out, int out_size) {
    const float* x = (const float*)d_in[0];   // (512, 1024)
    const float* T = (const float*)d_in[1];   // (1024, 1024)
    float* out = (float*)d_out;               // (512, 1088)

    prep_kernel<<<768, 256>>>(x, T, out);

    dim3 ggrid(AA / 64, NN / 64);             // (16, 8) = 128 blocks
    gemm_mma_kernel<<<ggrid, 128>>>();

    pairwise_kernel<<<NTILES, 512>>>(out);    // 136 blocks, single wave
}